// round 9
// baseline (speedup 1.0000x reference)
#include <cuda_runtime.h>
#include <cstdint>

#define NN 100
#define DD 128
#define CH 512
#define STRIDE 101
#define ARR (DD*STRIDE + 64)
#define NEG_INF __int_as_float(0xff800000)

struct Args { const void* p[10]; long sz[10]; int n; int batch; };

// chunk scratch per bb: [K_cn | V_cn | P_cn | Q_nc], each NN*DD floats (~105MB total)
__device__ float g_scr[(size_t)CH * 4 * NN * DD];
__device__ int g_psel, g_klen, g_ok, g_enc, g_widx[5];

// =====================================================================
// prep: device-side role detection by content. Guarded.
// =====================================================================
__global__ void prep_kernel(Args a)
{
    if (threadIdx.x != 0) return;
    int ok = 1;

    // enc = largest input
    int encIdx = 0; long mxs = -1;
    for (int i = 0; i < a.n; i++) if (a.sz[i] > mxs){ mxs = a.sz[i]; encIdx = i; }
    const long want = (long)a.batch * NN * DD;
    long scale = 1;
    if      (mxs == want)     scale = 1;
    else if (mxs == want * 4) scale = 4;       // byte-count fallback
    else ok = 0;

    // prefix: int32 values in [0,NN), >=2 distinct
    int psel = -1;
    for (int i = 0; i < a.n; i++){
        if (a.sz[i] / scale < 64) continue;
        const int* q = (const int*)a.p[i];
        bool good = true; int mn = 1 << 30, mxv = -1;
        for (int k = 0; k < 64; k++){
            const int v = q[k];
            if (v < 0 || v >= NN){ good = false; break; }
            mn = v < mn ? v : mn; mxv = v > mxv ? v : mxv;
        }
        if (good && mxv > mn){ psel = i; break; }
    }
    int klen = 10;
    if (psel >= 0 && a.batch > 0){
        const long kl = (a.sz[psel] / scale) / a.batch;
        if (kl >= 1 && kl <= NN) klen = (int)kl; else ok = 0;
    } else ok = 0;

    // problems: floats strictly in (0,1)
    int prob = -1;
    for (int i = 0; i < a.n; i++){
        if (i == encIdx || i == psel) continue;
        if (a.sz[i] / scale == (long)DD * DD) continue;
        const float* f = (const float*)a.p[i];
        bool good = true;
        for (int k = 0; k < 64; k++){
            const float v = f[k];
            if (!(v > 0.f && v < 1.f)){ good = false; break; }
        }
        if (good){ prob = i; break; }
    }

    // weights: DD*DD-sized inputs in index order
    int w[10]; int nw = 0;
    for (int i = 0; i < a.n; i++)
        if (a.sz[i] / scale == (long)DD * DD && nw < 10) w[nw++] = i;
    if (nw != 5){ ok = 0; w[0]=2; w[1]=3; w[2]=4; w[3]=5; w[4]=6; }

    const bool dict = (prob < 0) ? true : (prob < encIdx);
    // roles: 0=Wq_first 1=Wq_last 2=Wk 3=Wv 4=Wcomb
    if (dict){ g_widx[0]=w[0]; g_widx[1]=w[1]; g_widx[2]=w[2]; g_widx[3]=w[3]; g_widx[4]=w[4]; }
    else     { g_widx[0]=w[2]; g_widx[1]=w[3]; g_widx[2]=w[1]; g_widx[3]=w[4]; g_widx[4]=w[0]; }

    g_psel = psel; g_klen = klen; g_enc = encIdx; g_ok = ok;
}

// =====================================================================
// prefill: diagnostic marker (float 1.0) + prefix columns as FLOAT.
// =====================================================================
__global__ void prefill_kernel(Args a, float* __restrict__ out)
{
    const int b = blockIdx.x, tid = threadIdx.x;
    for (int j = tid; j < NN; j += blockDim.x) out[b*NN + j] = 1.0f;
    const int psel = g_psel, klen = g_klen;
    if (psel >= 0 && tid < klen){
        const int* pre = (const int*)a.p[psel];
        int p = pre[b*klen + tid];
        out[b*NN + tid] = (float)((p >= 0 && p < NN) ? p : 0);
    }
}

// =====================================================================
// gemm: grid (chunk, 4); 256 threads; scalar FFMA.
//  m=0: K_cn   m=1: Q_nc = E@Wq_last + q1   m=2: V_cn   m=3: P_cn = E@Wcomb^T
// =====================================================================
__global__ __launch_bounds__(256, 2) void gemm_kernel(Args a, int c0)
{
    if (!g_ok) return;
    __shared__ float Es[32*101 + 4];   // Es[dd][n]
    __shared__ float Ws[32*132];       // Ws[dd][c]
    __shared__ float q1s[128];

    const int bb = blockIdx.x, m = blockIdx.y;
    const int b = c0 + bb;
    const int tid = threadIdx.x;
    const int tx = tid & 31;           // c quad 4tx..4tx+3
    const int ty = tid >> 5;           // n = ty + 8k

    const int role = (m==0) ? 2 : (m==1) ? 1 : (m==2) ? 3 : 4;
    const float* W   = (const float*)a.p[g_widx[role]];
    const float* enc = (const float*)a.p[g_enc];
    const float* Eb  = enc + (size_t)b * (NN*DD);
    const int klen = g_klen;

    if (m == 1 && tid < 128){
        const int* pre = (const int*)a.p[g_psel];
        int last = pre[b*klen + (klen-1)];
        last = (last >= 0 && last < NN) ? last : 0;
        const float* er = Eb + last*DD;
        const float* Wqf = (const float*)a.p[g_widx[0]];
        float s = 0.f;
        for (int d = 0; d < DD; d++) s += er[d] * Wqf[d*DD + tid];
        q1s[tid] = s;
    }

    float acc[13][4];
    #pragma unroll
    for (int k = 0; k < 13; k++){ acc[k][0]=0.f; acc[k][1]=0.f; acc[k][2]=0.f; acc[k][3]=0.f; }

    for (int dch = 0; dch < 4; dch++){
        const int d0 = dch * 32;
        __syncthreads();
        for (int e = tid; e < 3200; e += 256){
            const int n = e >> 5, dd = e & 31;
            Es[dd*101 + n] = Eb[n*DD + d0 + dd];
        }
        if (m < 3){
            for (int e = tid; e < 4096; e += 256){
                const int dd = e >> 7, c = e & 127;
                Ws[dd*132 + c] = W[(d0+dd)*DD + c];
            }
        } else {
            for (int e = tid; e < 4096; e += 256){
                const int c = e >> 5, dd = e & 31;
                Ws[dd*132 + c] = W[c*DD + d0 + dd];      // Wcomb[c][d]
            }
        }
        __syncthreads();

        #pragma unroll 4
        for (int dd = 0; dd < 32; dd++){
            const float w0 = Ws[dd*132 + 4*tx+0];
            const float w1 = Ws[dd*132 + 4*tx+1];
            const float w2 = Ws[dd*132 + 4*tx+2];
            const float w3 = Ws[dd*132 + 4*tx+3];
            const float* er = Es + dd*101 + ty;
            #pragma unroll
            for (int k = 0; k < 13; k++){
                const float ev = er[8*k];                 // warp-broadcast
                acc[k][0] += ev*w0; acc[k][1] += ev*w1;
                acc[k][2] += ev*w2; acc[k][3] += ev*w3;
            }
        }
    }
    __syncthreads();

    float* base = g_scr + (size_t)bb * (4*NN*DD);
    if (m == 1){                                   // Q_nc (+q1)
        float* dst = base + 3*NN*DD;
        const float q0 = q1s[4*tx+0], q1 = q1s[4*tx+1], q2 = q1s[4*tx+2], q3 = q1s[4*tx+3];
        #pragma unroll
        for (int k = 0; k < 13; k++){
            const int n = ty + 8*k;
            if (n < NN){
                dst[n*DD + 4*tx+0] = acc[k][0] + q0;
                dst[n*DD + 4*tx+1] = acc[k][1] + q1;
                dst[n*DD + 4*tx+2] = acc[k][2] + q2;
                dst[n*DD + 4*tx+3] = acc[k][3] + q3;
            }
        }
    } else {                                       // K/V/P as [c][n]
        float* dst = base + ((m==0) ? 0 : (m==2) ? NN*DD : 2*NN*DD);
        #pragma unroll
        for (int k = 0; k < 13; k++){
            const int n = ty + 8*k;
            if (n < NN){
                dst[(4*tx+0)*NN + n] = acc[k][0];
                dst[(4*tx+1)*NN + n] = acc[k][1];
                dst[(4*tx+2)*NN + n] = acc[k][2];
                dst[(4*tx+3)*NN + n] = acc[k][3];
            }
        }
    }
}

// =====================================================================
// decode: K/V/P SMEM-resident (stride 101); Q row per step from L2.
// 256 threads. Writes FLOAT output.
// =====================================================================
__global__ __launch_bounds__(256, 1) void decode_kernel(Args a, int c0, float* __restrict__ out)
{
    if (!g_ok || g_psel < 0) return;
    extern __shared__ float sm[];
    float* Kt     = sm;                  // [128][101]
    float* Vt     = Kt + ARR;
    float* Pt     = Vt + ARR;
    float* att    = Pt + ARR;            // [8][104]
    float* psum   = att + 8*104;         // [2][128]
    float* mh     = psum + 256;          // [128]
    float* dpart  = mh + 128;            // [2][104]
    float* logits = dpart + 208;         // [104]
    float* maskv  = logits + 104;        // [104]
    float* Zs     = maskv + 104;         // [8]
    float* qcur   = Zs + 8;              // [128]
    int*   icur   = (int*)(qcur + 128);

    const int bb = blockIdx.x;
    const int b  = c0 + bb;
    const int tid = threadIdx.x;
    const int lane = tid & 31, wid = tid >> 5;
    const int klen = g_klen;
    const int* pre = (const int*)a.p[g_psel];

    const float* base = g_scr + (size_t)bb * (4*NN*DD);
    const float* Qb = base + 3*NN*DD;    // [n][c]

    // load K,V,P into smem (stride-101 rows)
    for (int e = tid; e < NN*DD; e += 256){
        const int c = e / NN, n = e % NN;
        Kt[c*STRIDE + n] = base[e];
        Vt[c*STRIDE + n] = base[NN*DD + e];
        Pt[c*STRIDE + n] = base[2*NN*DD + e];
    }

    if (tid < NN) maskv[tid] = 0.f;
    __syncthreads();
    if (tid < klen){
        int p = pre[b*klen + tid];
        p = (p >= 0 && p < NN) ? p : 0;
        maskv[p] = NEG_INF;
        out[b*NN + tid] = (float)p;
    }
    if (tid == 0){
        int last = pre[b*klen + (klen-1)];
        icur[0] = (last >= 0 && last < NN) ? last : 0;
    }
    __syncthreads();

    const int steps = NN - klen;
    for (int step = 0; step < steps; step++){
        const int cur = icur[0];
        if (tid < DD) qcur[tid] = Qb[cur*DD + tid];   // L2 hit
        __syncthreads();

        // ---- scores + softmax, warp per head ----
        {
            const int h = wid;
            const int n0 = lane, n1 = lane+32, n2 = lane+64, n3 = lane+96;
            const int n3i = (n3 < NN) ? n3 : 0;
            const float* Kh = Kt + h*16*STRIDE;
            float s0=0.f, s1=0.f, s2=0.f, s3=0.f;
            #pragma unroll
            for (int e = 0; e < 16; e++){
                const float qv = qcur[h*16 + e];
                const float* kr = Kh + e*STRIDE;
                s0 += qv*kr[n0]; s1 += qv*kr[n1]; s2 += qv*kr[n2]; s3 += qv*kr[n3i];
            }
            float v0 = s0*0.25f + maskv[n0];
            float v1 = s1*0.25f + maskv[n1];
            float v2 = s2*0.25f + maskv[n2];
            float v3 = (n3 < NN) ? (s3*0.25f + maskv[n3]) : NEG_INF;
            float mx = fmaxf(fmaxf(v0,v1), fmaxf(v2,v3));
            #pragma unroll
            for (int o = 16; o; o >>= 1) mx = fmaxf(mx, __shfl_xor_sync(0xffffffffu, mx, o));
            float w0 = expf(v0-mx), w1 = expf(v1-mx), w2 = expf(v2-mx);
            float w3 = (n3 < NN) ? expf(v3-mx) : 0.f;
            float zs = (w0+w1) + (w2+w3);
            #pragma unroll
            for (int o = 16; o; o >>= 1) zs += __shfl_xor_sync(0xffffffffu, zs, o);
            float* ar = att + h*104;
            ar[n0]=w0; ar[n1]=w1; ar[n2]=w2; if (n3 < NN) ar[n3]=w3;
            if (lane == 0) Zs[h] = zs;
        }
        __syncthreads();

        // ---- mh[c] = sum_n att[h(c)][n]*V[c][n] / Z ----
        {
            const int c = tid & 127, half = tid >> 7;
            const float* ar = att + (c >> 4)*104 + half*50;
            const float* vr = Vt + c*STRIDE + half*50;
            float p0 = 0.f, p1 = 0.f;
            #pragma unroll 5
            for (int i = 0; i < 50; i += 2){
                p0 += ar[i]   * vr[i];
                p1 += ar[i+1] * vr[i+1];
            }
            psum[half*128 + c] = p0 + p1;
        }
        __syncthreads();
        if (tid < 128) mh[tid] = (psum[tid] + psum[128+tid]) / Zs[tid >> 4];
        __syncthreads();

        // ---- sc[n] = mh . P[:,n] ----
        if (tid < 200){
            const int n = tid % 100, jh = tid / 100;
            const float* mr = mh + jh*64;
            const float* pr = Pt + (jh*64)*STRIDE + n;
            float a0 = 0.f, a1 = 0.f;
            #pragma unroll 8
            for (int j = 0; j < 64; j += 2){
                a0 += mr[j]   * pr[j*STRIDE];
                a1 += mr[j+1] * pr[(j+1)*STRIDE];
            }
            dpart[jh*104 + n] = a0 + a1;
        }
        __syncthreads();
        if (tid < 100){
            const float sc = (dpart[tid] + dpart[104+tid]) * 0.08838834764831845f; // 1/sqrt(128)
            logits[tid] = 10.f * tanhf(sc) + maskv[tid];
        }
        __syncthreads();

        // ---- argmax (first-max tie-break) + state update ----
        if (tid < 32){
            float best = NEG_INF; int bi = 0;
            #pragma unroll
            for (int j = 0; j < 4; j++){
                const int n = tid + 32*j;
                const float v = (n < NN) ? logits[n] : NEG_INF;
                if (v > best){ best = v; bi = n; }
            }
            #pragma unroll
            for (int o = 16; o; o >>= 1){
                const float ov = __shfl_down_sync(0xffffffffu, best, o);
                const int   oi = __shfl_down_sync(0xffffffffu, bi,   o);
                if (ov > best || (ov == best && oi < bi)){ best = ov; bi = oi; }
            }
            if (tid == 0){
                maskv[bi] = NEG_INF;
                icur[0] = bi;
                out[b*NN + klen + step] = (float)bi;
            }
        }
        __syncthreads();
    }
}

// =====================================================================
extern "C" void kernel_launch(void* const* d_in, const int* in_sizes, int n_in,
                              void* d_out, int out_size)
{
    Args a;
    for (int i = 0; i < 10; i++){
        a.p[i]  = (i < n_in) ? d_in[i] : d_in[0];
        a.sz[i] = (i < n_in) ? (long)in_sizes[i] : 0;
    }
    a.n = (n_in < 10) ? n_in : 10;
    a.batch = out_size / NN;          // in_sizes/out_size are element counts per stub
    if (a.batch < 1) a.batch = 1;
    float* out = (float*)d_out;       // __output__ treated as float32 (see theory)

    prep_kernel<<<1, 32>>>(a);
    prefill_kernel<<<a.batch, 128>>>(a, out);

    const int smem_bytes = (3*ARR + 8*104 + 256 + 128 + 208 + 104 + 104 + 8 + 128 + 8) * 4;
    (void)cudaFuncSetAttribute(decode_kernel, cudaFuncAttributeMaxDynamicSharedMemorySize, smem_bytes);

    for (int c0 = 0; c0 < a.batch; c0 += CH){
        const int cb = (a.batch - c0 < CH) ? (a.batch - c0) : CH;
        dim3 g(cb, 4);
        gemm_kernel<<<g, 256>>>(a, c0);
        decode_kernel<<<cb, 256, smem_bytes>>>(a, c0, out);
    }
}

// round 10
// speedup vs baseline: 1.3945x; 1.3945x over previous
#include <cuda_runtime.h>
#include <cstdint>

#define NN 100
#define DD 128
#define CH 2048                       // batches per chunk (full batch normally)
#define NEG_INF __int_as_float(0xff800000)

// per-batch table block in scratch AND in decode smem (floats):
// K [128][104] @0   V [128][108] @13312   P [100][132] @27136   Q [100][132] @40336
#define OFF_K 0
#define OFF_V 13312
#define OFF_P 27136
#define OFF_Q 40336
#define TBLK  53536                   // total table floats per batch (div by 4)

struct Args { const void* p[10]; long sz[10]; int n; int batch; };

__device__ float g_scr[(size_t)CH * TBLK];   // ~438MB, zero-init
__device__ int g_psel, g_klen, g_ok, g_enc, g_widx[5];

// ---------------- f32x2 helpers ----------------
__device__ __forceinline__ void ffma2(unsigned long long &d, unsigned long long a, unsigned long long b){
    asm("fma.rn.f32x2 %0, %1, %2, %0;" : "+l"(d) : "l"(a), "l"(b));
}
__device__ __forceinline__ unsigned long long dup2(float x){
    unsigned long long r; asm("mov.b64 %0, {%1, %1};" : "=l"(r) : "f"(x)); return r;
}
__device__ __forceinline__ void unpack2(unsigned long long v, float &lo, float &hi){
    asm("mov.b64 {%0, %1}, %2;" : "=f"(lo), "=f"(hi) : "l"(v));
}

// =====================================================================
// prep: device-side role detection by content. Guarded. (proven R9)
// =====================================================================
__global__ void prep_kernel(Args a)
{
    if (threadIdx.x != 0) return;
    int ok = 1;

    int encIdx = 0; long mxs = -1;
    for (int i = 0; i < a.n; i++) if (a.sz[i] > mxs){ mxs = a.sz[i]; encIdx = i; }
    const long want = (long)a.batch * NN * DD;
    long scale = 1;
    if      (mxs == want)     scale = 1;
    else if (mxs == want * 4) scale = 4;
    else ok = 0;

    int psel = -1;
    for (int i = 0; i < a.n; i++){
        if (a.sz[i] / scale < 64) continue;
        const int* q = (const int*)a.p[i];
        bool good = true; int mn = 1 << 30, mxv = -1;
        for (int k = 0; k < 64; k++){
            const int v = q[k];
            if (v < 0 || v >= NN){ good = false; break; }
            mn = v < mn ? v : mn; mxv = v > mxv ? v : mxv;
        }
        if (good && mxv > mn){ psel = i; break; }
    }
    int klen = 10;
    if (psel >= 0 && a.batch > 0){
        const long kl = (a.sz[psel] / scale) / a.batch;
        if (kl >= 1 && kl <= NN) klen = (int)kl; else ok = 0;
    } else ok = 0;

    int prob = -1;
    for (int i = 0; i < a.n; i++){
        if (i == encIdx || i == psel) continue;
        if (a.sz[i] / scale == (long)DD * DD) continue;
        const float* f = (const float*)a.p[i];
        bool good = true;
        for (int k = 0; k < 64; k++){
            const float v = f[k];
            if (!(v > 0.f && v < 1.f)){ good = false; break; }
        }
        if (good){ prob = i; break; }
    }

    int w[10]; int nw = 0;
    for (int i = 0; i < a.n; i++)
        if (a.sz[i] / scale == (long)DD * DD && nw < 10) w[nw++] = i;
    if (nw != 5){ ok = 0; w[0]=2; w[1]=3; w[2]=4; w[3]=5; w[4]=6; }

    const bool dict = (prob < 0) ? true : (prob < encIdx);
    // roles: 0=Wq_first 1=Wq_last 2=Wk 3=Wv 4=Wcomb
    if (dict){ g_widx[0]=w[0]; g_widx[1]=w[1]; g_widx[2]=w[2]; g_widx[3]=w[3]; g_widx[4]=w[4]; }
    else     { g_widx[0]=w[2]; g_widx[1]=w[3]; g_widx[2]=w[1]; g_widx[3]=w[4]; g_widx[4]=w[0]; }

    g_psel = psel; g_klen = klen; g_enc = encIdx; g_ok = ok;
}

// =====================================================================
// prefill: diagnostic floor — prefix cols + 1.0f elsewhere.
// =====================================================================
__global__ void prefill_kernel(Args a, float* __restrict__ out)
{
    const int b = blockIdx.x, tid = threadIdx.x;
    for (int j = tid; j < NN; j += blockDim.x) out[b*NN + j] = 1.0f;
    const int psel = g_psel, klen = g_klen;
    if (psel >= 0 && tid < klen){
        const int* pre = (const int*)a.p[psel];
        int p = pre[b*klen + tid];
        out[b*NN + tid] = (float)((p >= 0 && p < NN) ? p : 0);
    }
}

// =====================================================================
// gemm: grid (chunk, 4); 256 threads; f32x2 FMA core (R1 design).
//  m=0: K_cn -> [c][104]   m=1: Q_nc(+q1) -> [n][132]
//  m=2: V_cn -> [c][108]   m=3: P_nc = E@Wcomb^T -> [n][132]
// thread (tx,ty): tx -> c quad 4tx..4tx+3; ty -> n-pairs n0 = 2*(ty+8k), k<7.
// =====================================================================
__global__ __launch_bounds__(256, 2) void gemm_kernel(Args a, int c0)
{
    if (!g_ok) return;
    __shared__ __align__(16) float Es[32*102 + 16];   // Es[dd][n], 8B-aligned pairs
    __shared__ __align__(16) float Ws[32*132];        // Ws[dd][c], 16B rows
    __shared__ __align__(16) float q1s[128];

    const int bb = blockIdx.x, m = blockIdx.y;
    const int b = c0 + bb;
    const int tid = threadIdx.x;
    const int tx = tid & 31;
    const int ty = tid >> 5;

    const int role = (m==0) ? 2 : (m==1) ? 1 : (m==2) ? 3 : 4;
    const float* W   = (const float*)a.p[g_widx[role]];
    const float* enc = (const float*)a.p[g_enc];
    const float* Eb  = enc + (size_t)b * (NN*DD);
    const int klen = g_klen;

    if (m == 1 && tid < 128){
        const int* pre = (const int*)a.p[g_psel];
        int last = pre[b*klen + (klen-1)];
        last = (last >= 0 && last < NN) ? last : 0;
        const float* er = Eb + last*DD;
        const float* Wqf = (const float*)a.p[g_widx[0]];
        float s = 0.f;
        for (int d = 0; d < DD; d++) s += er[d] * Wqf[d*DD + tid];
        q1s[tid] = s;
    }

    unsigned long long acc[7][4];
    #pragma unroll
    for (int k = 0; k < 7; k++){ acc[k][0]=0ull; acc[k][1]=0ull; acc[k][2]=0ull; acc[k][3]=0ull; }

    for (int dch = 0; dch < 4; dch++){
        const int d0 = dch * 32;
        __syncthreads();
        for (int e = tid; e < 3200; e += 256){
            const int n = e >> 5, dd = e & 31;
            Es[dd*102 + n] = Eb[n*DD + d0 + dd];
        }
        if (m < 3){
            for (int e = tid; e < 4096; e += 256){
                const int dd = e >> 7, c = e & 127;
                Ws[dd*132 + c] = W[(d0+dd)*DD + c];
            }
        } else {
            for (int e = tid; e < 4096; e += 256){
                const int c = e >> 5, dd = e & 31;
                Ws[dd*132 + c] = W[c*DD + d0 + dd];      // Wcomb[c][d]
            }
        }
        __syncthreads();

        #pragma unroll 4
        for (int dd = 0; dd < 32; dd++){
            const float4 w4 = *(const float4*)(Ws + dd*132 + 4*tx);
            const unsigned long long w0 = dup2(w4.x), w1 = dup2(w4.y),
                                     w2 = dup2(w4.z), w3 = dup2(w4.w);
            const float* er = Es + dd*102 + 2*ty;
            #pragma unroll
            for (int k = 0; k < 7; k++){
                const unsigned long long e2 = *(const unsigned long long*)(er + 16*k); // 8B aligned
                ffma2(acc[k][0], e2, w0);
                ffma2(acc[k][1], e2, w1);
                ffma2(acc[k][2], e2, w2);
                ffma2(acc[k][3], e2, w3);
            }
        }
    }
    __syncthreads();

    float* base = g_scr + (size_t)bb * TBLK;
    float4 q1v = make_float4(0.f,0.f,0.f,0.f);
    if (m == 1) q1v = *(const float4*)(q1s + 4*tx);

    #pragma unroll
    for (int k = 0; k < 7; k++){
        const int n0 = 2*(ty + 8*k);
        if (n0 >= NN) continue;
        const int n1 = n0 + 1;
        float lo0,hi0,lo1,hi1,lo2,hi2,lo3,hi3;
        unpack2(acc[k][0], lo0, hi0);
        unpack2(acc[k][1], lo1, hi1);
        unpack2(acc[k][2], lo2, hi2);
        unpack2(acc[k][3], lo3, hi3);
        if (m == 0){
            float* K = base + OFF_K;
            K[(4*tx+0)*104 + n0] = lo0;  K[(4*tx+0)*104 + n1] = hi0;
            K[(4*tx+1)*104 + n0] = lo1;  K[(4*tx+1)*104 + n1] = hi1;
            K[(4*tx+2)*104 + n0] = lo2;  K[(4*tx+2)*104 + n1] = hi2;
            K[(4*tx+3)*104 + n0] = lo3;  K[(4*tx+3)*104 + n1] = hi3;
        } else if (m == 2){
            float* V = base + OFF_V;
            V[(4*tx+0)*108 + n0] = lo0;  V[(4*tx+0)*108 + n1] = hi0;
            V[(4*tx+1)*108 + n0] = lo1;  V[(4*tx+1)*108 + n1] = hi1;
            V[(4*tx+2)*108 + n0] = lo2;  V[(4*tx+2)*108 + n1] = hi2;
            V[(4*tx+3)*108 + n0] = lo3;  V[(4*tx+3)*108 + n1] = hi3;
        } else if (m == 3){
            float* P = base + OFF_P;
            *(float4*)(P + n0*132 + 4*tx) = make_float4(lo0,lo1,lo2,lo3);
            *(float4*)(P + n1*132 + 4*tx) = make_float4(hi0,hi1,hi2,hi3);
        } else {
            float* Q = base + OFF_Q;
            *(float4*)(Q + n0*132 + 4*tx) = make_float4(lo0+q1v.x, lo1+q1v.y, lo2+q1v.z, lo3+q1v.w);
            *(float4*)(Q + n1*132 + 4*tx) = make_float4(hi0+q1v.x, hi1+q1v.y, hi2+q1v.z, hi3+q1v.w);
        }
    }
}

// =====================================================================
// decode: all tables SMEM-resident (aligned padded rows); vectorized
// LDS.128 + f32x2 phases. 256 threads, 1 CTA/SM.
// =====================================================================
__global__ __launch_bounds__(256, 1) void decode_kernel(Args a, int c0, float* __restrict__ out)
{
    if (!g_ok || g_psel < 0) return;
    extern __shared__ __align__(16) float sm[];
    float* Kt    = sm + OFF_K;           // [128][104]
    float* Vt    = sm + OFF_V;           // [128][108]
    float* Pt    = sm + OFF_P;           // [100][132]
    float* Qt    = sm + OFF_Q;           // [100][132]
    float* att   = sm + TBLK;            // [8][112]      @53536
    float* psum  = att + 8*112;          // [2][128]      @54432
    float* mh    = psum + 256;           // [128]         @54688
    float* dpart = mh + 128;             // [2][104]      @54816
    float* maskv = dpart + 208;          // [104]         @55024
    float* Zs    = maskv + 104;          // [8]           @55128
    int*   icur  = (int*)(Zs + 8);

    const int bb = blockIdx.x;
    const int b  = c0 + bb;
    const int tid = threadIdx.x;
    const int lane = tid & 31, wid = tid >> 5;
    const int klen = g_klen;
    const int* pre = (const int*)a.p[g_psel];

    // single contiguous copy: scratch block layout == smem layout
    {
        const float4* src = (const float4*)(g_scr + (size_t)bb * TBLK);
        float4* dst = (float4*)sm;
        for (int i = tid; i < TBLK/4; i += 256) dst[i] = src[i];
    }
    if (tid < 104) maskv[tid] = 0.f;
    __syncthreads();
    if (tid < klen){
        int p = pre[b*klen + tid];
        p = (p >= 0 && p < NN) ? p : 0;
        maskv[p] = NEG_INF;
        out[b*NN + tid] = (float)p;
    }
    if (tid == 0){
        int last = pre[b*klen + (klen-1)];
        icur[0] = (last >= 0 && last < NN) ? last : 0;
    }
    __syncthreads();

    // phase-C/D per-thread constants
    const int cC = tid & 127, halfC = tid >> 7;
    const int nqBeg = halfC ? 13 : 0, nqEnd = halfC ? 25 : 13;
    const float* VrowC = Vt + cC*108;
    const float* arC   = att + (cC >> 4)*112;
    const int nD = tid % 100, jhD = tid / 100;   // valid when tid<200
    const float* ProwD = Pt + nD*132 + jhD*64;
    const float* mhD   = mh + jhD*64;

    const int steps = NN - klen;
    for (int step = 0; step < steps; step++){
        const int cur = icur[0];

        // ---- Phase A: scores + softmax weights, warp per head, quad per lane ----
        {
            const int h = wid;
            const int nq = (lane < 25) ? lane : 24;
            const bool valid = (lane < 25);
            const float* qrow = Qt + cur*132 + h*16;
            const float* kq = Kt + (h*16)*104 + 4*nq;
            unsigned long long a0 = 0ull, a1 = 0ull;
            #pragma unroll
            for (int e = 0; e < 16; e++){
                const unsigned long long q2 = dup2(qrow[e]);
                const ulonglong2 k2 = *(const ulonglong2*)(kq + e*104);
                ffma2(a0, q2, k2.x);
                ffma2(a1, q2, k2.y);
            }
            float s0,s1,s2,s3;
            unpack2(a0, s0, s1);
            unpack2(a1, s2, s3);
            const float4 m4 = *(const float4*)(maskv + 4*nq);
            float v0 = valid ? (s0*0.25f + m4.x) : NEG_INF;
            float v1 = valid ? (s1*0.25f + m4.y) : NEG_INF;
            float v2 = valid ? (s2*0.25f + m4.z) : NEG_INF;
            float v3 = valid ? (s3*0.25f + m4.w) : NEG_INF;
            float mx = fmaxf(fmaxf(v0,v1), fmaxf(v2,v3));
            #pragma unroll
            for (int o = 16; o; o >>= 1) mx = fmaxf(mx, __shfl_xor_sync(0xffffffffu, mx, o));
            float w0 = valid ? expf(v0-mx) : 0.f;
            float w1 = valid ? expf(v1-mx) : 0.f;
            float w2 = valid ? expf(v2-mx) : 0.f;
            float w3 = valid ? expf(v3-mx) : 0.f;
            float zs = (w0+w1) + (w2+w3);
            #pragma unroll
            for (int o = 16; o; o >>= 1) zs += __shfl_xor_sync(0xffffffffu, zs, o);
            if (valid) *(float4*)(att + h*112 + 4*nq) = make_float4(w0,w1,w2,w3);
            if (lane == 0) Zs[h] = zs;
        }
        __syncthreads();

        // ---- Phase C: mh[c] = sum_n att[h(c)][n]*V[c][n] (vectorized) ----
        {
            unsigned long long a0 = 0ull, a1 = 0ull;
            for (int nq = nqBeg; nq < nqEnd; nq++){
                const ulonglong2 av = *(const ulonglong2*)(arC + 4*nq);
                const ulonglong2 vv = *(const ulonglong2*)(VrowC + 4*nq);
                ffma2(a0, av.x, vv.x);
                ffma2(a1, av.y, vv.y);
            }
            float s0,s1,s2,s3;
            unpack2(a0, s0, s1);
            unpack2(a1, s2, s3);
            psum[halfC*128 + cC] = (s0+s1) + (s2+s3);
        }
        __syncthreads();
        if (tid < 128) mh[tid] = (psum[tid] + psum[128+tid]) / Zs[tid >> 4];
        __syncthreads();

        // ---- Phase D: sc[n] = mh . P[n][:] (vectorized, j-halved) ----
        if (tid < 200){
            unsigned long long a0 = 0ull, a1 = 0ull;
            #pragma unroll
            for (int jq = 0; jq < 16; jq++){
                const ulonglong2 mq = *(const ulonglong2*)(mhD + 4*jq);
                const ulonglong2 pq = *(const ulonglong2*)(ProwD + 4*jq);
                ffma2(a0, mq.x, pq.x);
                ffma2(a1, mq.y, pq.y);
            }
            float s0,s1,s2,s3;
            unpack2(a0, s0, s1);
            unpack2(a1, s2, s3);
            dpart[jhD*104 + nD] = (s0+s1) + (s2+s3);
        }
        __syncthreads();

        // ---- Phase E: logits inline + argmax (first-max tie-break) ----
        if (tid < 32){
            float best = NEG_INF; int bi = 0;
            #pragma unroll
            for (int j = 0; j < 4; j++){
                const int n = tid + 32*j;
                float v = NEG_INF;
                if (n < NN){
                    const float sc = (dpart[n] + dpart[104+n]) * 0.08838834764831845f; // 1/sqrt(128)
                    v = 10.f * tanhf(sc) + maskv[n];
                }
                if (v > best){ best = v; bi = n; }
            }
            #pragma unroll
            for (int o = 16; o; o >>= 1){
                const float ov = __shfl_down_sync(0xffffffffu, best, o);
                const int   oi = __shfl_down_sync(0xffffffffu, bi,   o);
                if (ov > best || (ov == best && oi < bi)){ best = ov; bi = oi; }
            }
            if (tid == 0){
                maskv[bi] = NEG_INF;
                icur[0] = bi;
                out[b*NN + klen + step] = (float)bi;
            }
        }
        __syncthreads();
    }
}

// =====================================================================
extern "C" void kernel_launch(void* const* d_in, const int* in_sizes, int n_in,
                              void* d_out, int out_size)
{
    Args a;
    for (int i = 0; i < 10; i++){
        a.p[i]  = (i < n_in) ? d_in[i] : d_in[0];
        a.sz[i] = (i < n_in) ? (long)in_sizes[i] : 0;
    }
    a.n = (n_in < 10) ? n_in : 10;
    a.batch = out_size / NN;
    if (a.batch < 1) a.batch = 1;
    float* out = (float*)d_out;

    prep_kernel<<<1, 32>>>(a);
    prefill_kernel<<<a.batch, 128>>>(a, out);

    const int smem_bytes = (TBLK + 8*112 + 256 + 128 + 208 + 104 + 8 + 4) * 4;  // ~220.6KB
    (void)cudaFuncSetAttribute(decode_kernel, cudaFuncAttributeMaxDynamicSharedMemorySize, smem_bytes);

    for (int c0 = 0; c0 < a.batch; c0 += CH){
        const int cb = (a.batch - c0 < CH) ? (a.batch - c0) : CH;
        dim3 g(cb, 4);
        gemm_kernel<<<g, 256>>>(a, c0);
        decode_kernel<<<cb, 256, smem_bytes>>>(a, c0, out);
    }
}